// round 11
// baseline (speedup 1.0000x reference)
#include <cuda_runtime.h>
#include <cstdint>

// R-MAC over x[32, 2048, 32, 32] -> out[32, 2048].
// 19 static regions (H=W=32): 1x full (32x32), 6x 21x21 (rows {0,5,11} x cols
// {0,11}), 12x 16x16 (rows {0,5,10,16} x cols {0,8,16}).
// Column segments: s1=[0,21) s2=[11,32) s3=[0,16) s4=[8,24) s5=[16,32).
// Row-block decomposition:
//   segs 1,2 (fam B): blocks [0,5)[5,11)[11,16)[16,21)[21,26)[26,32)
//   segs 3,4,5 (fam C): blocks [0,5)[5,10)[10,16)[16,21)[21,26)[26,32)
// Full image = max over bmbuf of segs 1,2 (cols [0,21)u[11,32)=[0,32), all rows).

#define WPB   8
#define DEPTH 3
#define TPW   8
#define NTILES (32 * 2048)
#define DYN_SMEM (WPB * DEPTH * 4096)

__constant__ int c_start[2][6] = {{0, 5, 11, 16, 21, 26}, {0, 5, 10, 16, 21, 26}};
__constant__ int c_sz6[2][6]   = {{0, 1, 0, 0, 0, 1},     {0, 0, 1, 0, 0, 1}};
__constant__ int c_rbase[19] = {0, 0, 6, 1, 7, 2, 8,
                                12, 18, 24, 13, 19, 25, 14, 20, 26, 15, 21, 27};
__constant__ int c_rcnt4[19] = {0, 1, 1, 1, 1, 1, 1, 0, 0, 0, 0, 0, 0, 0, 0, 0, 0, 0, 0};

__device__ __forceinline__ void cpa16(uint32_t dst_smem, const void* src) {
    asm volatile("cp.async.cg.shared.global [%0], [%1], 16;"
                 :: "r"(dst_smem), "l"(src) : "memory");
}
__device__ __forceinline__ void cpa_commit() {
    asm volatile("cp.async.commit_group;" ::: "memory");
}
template <int N>
__device__ __forceinline__ void cpa_wait() {
    asm volatile("cp.async.wait_group %0;" :: "n"(N) : "memory");
}
// Per-thread groups committed before the wait at iter `it` is
// min(TPW, DEPTH + it); group #it must be complete, so wait until
// <= committed - (it+1) groups pending. Constant-folds under full unroll.
__device__ __forceinline__ void cpa_wait_iter(int it) {
    const int committed = (DEPTH + it < TPW) ? (DEPTH + it) : TPW;
    const int n = committed - (it + 1);
    switch (n) {
        case 0: cpa_wait<0>(); break;
        case 1: cpa_wait<1>(); break;
        case 2: cpa_wait<2>(); break;
        default: cpa_wait<0>(); break;
    }
}

__global__ __launch_bounds__(32 * WPB)
void rmac_kernel(const float* __restrict__ x, float* __restrict__ out) {
    extern __shared__ float4 ring[];      // [WPB][DEPTH][256] float4 = 96 KB
    __shared__ float segm[WPB][32 * 7];   // per-row segment maxes, stride 7
    __shared__ float bmbuf[WPB][32];      // 30 (seg,block) maxes
    __shared__ float rsum[WPB][20];       // region maxes for the final sum

    const int wib  = threadIdx.x >> 5;
    const int lane = threadIdx.x & 31;
    const int wg   = blockIdx.x * WPB + wib;
    const size_t tbase = (size_t)wg * TPW;

    const float4* __restrict__ x4 = reinterpret_cast<const float4*>(x);
    const uint32_t ring0 =
        (uint32_t)__cvta_generic_to_shared(ring) + (uint32_t)(wib * DEPTH * 4096);

    // Write mapping: lane l, op k holds tile quad (k*32+l) = row 4k+(l>>3),
    // 16B-group c=l&7. Store XOR-swizzled: group slot c ^ (row&7).
    const int wrow_a = lane >> 3;
    const int wc     = lane & 7;

    auto issue_tile = [&](int slot, int it) {
        const float4* src = x4 + (tbase + it) * 256;
        const uint32_t sb = ring0 + (uint32_t)slot * 4096;
#pragma unroll
        for (int k = 0; k < 8; k++) {
            const int row = 4 * k + wrow_a;
            const uint32_t dst = sb + (uint32_t)((row * 8 + (wc ^ (row & 7))) * 16);
            cpa16(dst, src + k * 32 + lane);
        }
        cpa_commit();
    };

    // Prologue: fill the ring (groups 0..DEPTH-1 = tiles 0..DEPTH-1).
#pragma unroll
    for (int d = 0; d < DEPTH; d++) issue_tile(d, d);

    const int r  = lane;                  // this lane reduces row r
    const int rx = r & 7;

#pragma unroll
    for (int it = 0; it < TPW; it++) {
        const int slot = it % DEPTH;
        cpa_wait_iter(it);                // guarantee group #it (this slot) done
        __syncwarp();                     // publish all lanes' copies

        // ---- Row reduce straight from swizzled smem (lane = row) ----
        const float4* B = ring + (size_t)(wib * DEPTH + slot) * 256 + r * 8;
        float4 q[8];
#pragma unroll
        for (int g = 0; g < 8; g++) q[g] = B[g ^ rx];   // conflict-free LDS.128
        float m[8];
#pragma unroll
        for (int g = 0; g < 8; g++)
            m[g] = fmaxf(fmaxf(q[g].x, q[g].y), fmaxf(q[g].z, q[g].w));
        const float r11 = q[2].w;         // col 11
        const float r20 = q[5].x;         // col 20

        const float s3 = fmaxf(fmaxf(m[0], m[1]), fmaxf(m[2], m[3]));  // [0,16)
        const float s4 = fmaxf(fmaxf(m[2], m[3]), fmaxf(m[4], m[5]));  // [8,24)
        const float s5 = fmaxf(fmaxf(m[4], m[5]), fmaxf(m[6], m[7]));  // [16,32)
        const float s1 = fmaxf(s3, fmaxf(m[4], r20));                  // [0,21)
        const float s2 = fmaxf(r11, fmaxf(m[3], s5));                  // [11,32)

        float* sd = segm[wib] + r * 7;    // stride 7: conflict-free
        sd[1] = s1; sd[2] = s2; sd[3] = s3; sd[4] = s4; sd[5] = s5;
        __syncwarp();                     // all lanes done reading ring + segm ready

        // Ring slot fully consumed -> refill it (commit group DEPTH+it).
        if (it + DEPTH < TPW) issue_tile(slot, it + DEPTH);

        // ---- 30 (segment, row-block) maxes ----
        if (lane < 30) {
            const int s   = 1 + lane / 6;
            const int blk = lane % 6;
            const int fam = (s >= 3);
            const int st  = c_start[fam][blk];
            const float* sp = segm[wib] + s;
            float bm = sp[st * 7];
#pragma unroll
            for (int qq = 1; qq < 5; qq++) bm = fmaxf(bm, sp[(st + qq) * 7]);
            if (c_sz6[fam][blk]) bm = fmaxf(bm, sp[(st + 5) * 7]);
            bmbuf[wib][lane] = bm;
        }
        __syncwarp();

        // ---- Region maxes into rsum (lanes 0/19 zero-pad) ----
        if (lane >= 1 && lane < 19) {
            const float* bp = bmbuf[wib];
            const int base = c_rbase[lane];
            float mm = fmaxf(fmaxf(bp[base], bp[base + 1]), bp[base + 2]);
            if (c_rcnt4[lane]) mm = fmaxf(mm, bp[base + 3]);
            rsum[wib][lane] = mm;
        } else if (lane == 19) {
            rsum[wib][19] = 0.0f;
        } else if (lane == 0) {
            rsum[wib][0] = 0.0f;
        }
        __syncwarp();

        // ---- Lane 0: full-image max + sum of 19 regions ----
        if (lane == 0) {
            const float4 b0 = *reinterpret_cast<const float4*>(&bmbuf[wib][0]);
            const float4 b1 = *reinterpret_cast<const float4*>(&bmbuf[wib][4]);
            const float4 b2 = *reinterpret_cast<const float4*>(&bmbuf[wib][8]);
            float full = fmaxf(fmaxf(fmaxf(b0.x, b0.y), fmaxf(b0.z, b0.w)),
                               fmaxf(fmaxf(b1.x, b1.y), fmaxf(b1.z, b1.w)));
            full = fmaxf(full, fmaxf(fmaxf(b2.x, b2.y), fmaxf(b2.z, b2.w)));

            const float4 q0 = *reinterpret_cast<const float4*>(&rsum[wib][0]);
            const float4 q1 = *reinterpret_cast<const float4*>(&rsum[wib][4]);
            const float4 q2 = *reinterpret_cast<const float4*>(&rsum[wib][8]);
            const float4 q3 = *reinterpret_cast<const float4*>(&rsum[wib][12]);
            const float4 q4 = *reinterpret_cast<const float4*>(&rsum[wib][16]);
            float acc = ((q0.x + q0.y) + (q0.z + q0.w))
                      + ((q1.x + q1.y) + (q1.z + q1.w))
                      + ((q2.x + q2.y) + (q2.z + q2.w))
                      + ((q3.x + q3.y) + (q3.z + q3.w))
                      + ((q4.x + q4.y) + (q4.z + q4.w))
                      + full;
            out[tbase + it] = acc;
        }
        __syncwarp();
    }
}

extern "C" void kernel_launch(void* const* d_in, const int* in_sizes, int n_in,
                              void* d_out, int out_size) {
    const float* x = (const float*)d_in[0];
    float* out = (float*)d_out;
    (void)in_sizes; (void)n_in; (void)out_size;
    // Opt-in dynamic smem above 48KB (idempotent host call; no allocation).
    cudaFuncSetAttribute(rmac_kernel,
                         cudaFuncAttributeMaxDynamicSharedMemorySize, DYN_SMEM);
    rmac_kernel<<<NTILES / (WPB * TPW), 32 * WPB, DYN_SMEM>>>(x, out);
}

// round 12
// speedup vs baseline: 1.3820x; 1.3820x over previous
#include <cuda_runtime.h>
#include <cstdint>

// R-MAC over x[32, 2048, 32, 32] -> out[32, 2048].
// 19 static regions (H=W=32): 1x full (32x32), 6x 21x21 (rows {0,5,11} x cols
// {0,11}), 12x 16x16 (rows {0,5,10,16} x cols {0,8,16}).
// Column segments: s1=[0,21) s2=[11,32) s3=[0,16) s4=[8,24) s5=[16,32).
// Row-block decomposition:
//   segs 1,2 (fam B): blocks [0,5)[5,11)[11,16)[16,21)[21,26)[26,32)
//   segs 3,4,5 (fam C): blocks [0,5)[5,10)[10,16)[16,21)[21,26)[26,32)
// Full image = max over bmbuf of segs 1,2 (cols [0,21)u[11,32)=[0,32), all rows).
//
// R12 design: pure-burst pipeline. Each warp cp.async-bursts ALL 4 of its
// tiles (16 KB, 4 commit groups) in the prologue, then drains with waits
// {3,2,1,0}. No refills -> load issue is never serialized behind consumption.
// 64 KB ring + ~4.5 KB static -> 3 blocks/SM; grid 4096 -> ~9 waves of short
// blocks so prologue bursts are injected continuously on every SM.

#define WPB   4
#define DEPTH 4
#define TPW   4
#define NTILES (32 * 2048)
#define DYN_SMEM (WPB * DEPTH * 4096)

__constant__ int c_start[2][6] = {{0, 5, 11, 16, 21, 26}, {0, 5, 10, 16, 21, 26}};
__constant__ int c_sz6[2][6]   = {{0, 1, 0, 0, 0, 1},     {0, 0, 1, 0, 0, 1}};
__constant__ int c_rbase[19] = {0, 0, 6, 1, 7, 2, 8,
                                12, 18, 24, 13, 19, 25, 14, 20, 26, 15, 21, 27};
__constant__ int c_rcnt4[19] = {0, 1, 1, 1, 1, 1, 1, 0, 0, 0, 0, 0, 0, 0, 0, 0, 0, 0, 0};

__device__ __forceinline__ void cpa16(uint32_t dst_smem, const void* src) {
    asm volatile("cp.async.cg.shared.global [%0], [%1], 16;"
                 :: "r"(dst_smem), "l"(src) : "memory");
}
__device__ __forceinline__ void cpa_commit() {
    asm volatile("cp.async.commit_group;" ::: "memory");
}
template <int N>
__device__ __forceinline__ void cpa_wait() {
    asm volatile("cp.async.wait_group %0;" :: "n"(N) : "memory");
}
// All TPW groups are committed up front; before consuming tile #it we need
// <= TPW-1-it groups still pending. Constant-folds under full unroll.
__device__ __forceinline__ void cpa_wait_iter(int it) {
    switch (TPW - 1 - it) {
        case 0: cpa_wait<0>(); break;
        case 1: cpa_wait<1>(); break;
        case 2: cpa_wait<2>(); break;
        case 3: cpa_wait<3>(); break;
        default: cpa_wait<0>(); break;
    }
}

__global__ __launch_bounds__(32 * WPB)
void rmac_kernel(const float* __restrict__ x, float* __restrict__ out) {
    extern __shared__ float4 ring[];      // [WPB][DEPTH][256] float4 = 64 KB
    __shared__ float segm[WPB][32 * 7];   // per-row segment maxes, stride 7
    __shared__ float bmbuf[WPB][32];      // 30 (seg,block) maxes
    __shared__ float rsum[WPB][20];       // region maxes for the final sum

    const int wib  = threadIdx.x >> 5;
    const int lane = threadIdx.x & 31;
    const int wg   = blockIdx.x * WPB + wib;
    const size_t tbase = (size_t)wg * TPW;

    const float4* __restrict__ x4 = reinterpret_cast<const float4*>(x);
    const uint32_t ring0 =
        (uint32_t)__cvta_generic_to_shared(ring) + (uint32_t)(wib * DEPTH * 4096);

    // Write mapping: lane l, op k holds tile quad (k*32+l) = row 4k+(l>>3),
    // 16B-group c=l&7. Store XOR-swizzled: group slot c ^ (row&7).
    const int wrow_a = lane >> 3;
    const int wc     = lane & 7;

    // ---- Prologue burst: issue ALL TPW tiles (one commit group each) ----
#pragma unroll
    for (int d = 0; d < TPW; d++) {
        const float4* src = x4 + (tbase + d) * 256;
        const uint32_t sb = ring0 + (uint32_t)d * 4096;
#pragma unroll
        for (int k = 0; k < 8; k++) {
            const int row = 4 * k + wrow_a;
            const uint32_t dst = sb + (uint32_t)((row * 8 + (wc ^ (row & 7))) * 16);
            cpa16(dst, src + k * 32 + lane);
        }
        cpa_commit();
    }

    const int r  = lane;                  // this lane reduces row r
    const int rx = r & 7;

#pragma unroll
    for (int it = 0; it < TPW; it++) {
        cpa_wait_iter(it);                // tile #it complete (slot == it)
        __syncwarp();                     // publish all lanes' copies

        // ---- Row reduce straight from swizzled smem (lane = row) ----
        const float4* B = ring + (size_t)(wib * DEPTH + it) * 256 + r * 8;
        float4 q[8];
#pragma unroll
        for (int g = 0; g < 8; g++) q[g] = B[g ^ rx];   // conflict-free LDS.128
        float m[8];
#pragma unroll
        for (int g = 0; g < 8; g++)
            m[g] = fmaxf(fmaxf(q[g].x, q[g].y), fmaxf(q[g].z, q[g].w));
        const float r11 = q[2].w;         // col 11
        const float r20 = q[5].x;         // col 20

        const float s3 = fmaxf(fmaxf(m[0], m[1]), fmaxf(m[2], m[3]));  // [0,16)
        const float s4 = fmaxf(fmaxf(m[2], m[3]), fmaxf(m[4], m[5]));  // [8,24)
        const float s5 = fmaxf(fmaxf(m[4], m[5]), fmaxf(m[6], m[7]));  // [16,32)
        const float s1 = fmaxf(s3, fmaxf(m[4], r20));                  // [0,21)
        const float s2 = fmaxf(r11, fmaxf(m[3], s5));                  // [11,32)

        float* sd = segm[wib] + r * 7;    // stride 7: conflict-free
        sd[1] = s1; sd[2] = s2; sd[3] = s3; sd[4] = s4; sd[5] = s5;
        __syncwarp();

        // ---- 30 (segment, row-block) maxes ----
        if (lane < 30) {
            const int s   = 1 + lane / 6;
            const int blk = lane % 6;
            const int fam = (s >= 3);
            const int st  = c_start[fam][blk];
            const float* sp = segm[wib] + s;
            float bm = sp[st * 7];
#pragma unroll
            for (int qq = 1; qq < 5; qq++) bm = fmaxf(bm, sp[(st + qq) * 7]);
            if (c_sz6[fam][blk]) bm = fmaxf(bm, sp[(st + 5) * 7]);
            bmbuf[wib][lane] = bm;
        }
        __syncwarp();

        // ---- Region maxes into rsum (lanes 0/19 zero-pad) ----
        if (lane >= 1 && lane < 19) {
            const float* bp = bmbuf[wib];
            const int base = c_rbase[lane];
            float mm = fmaxf(fmaxf(bp[base], bp[base + 1]), bp[base + 2]);
            if (c_rcnt4[lane]) mm = fmaxf(mm, bp[base + 3]);
            rsum[wib][lane] = mm;
        } else if (lane == 19) {
            rsum[wib][19] = 0.0f;
        } else if (lane == 0) {
            rsum[wib][0] = 0.0f;
        }
        __syncwarp();

        // ---- Lane 0: full-image max + sum of 19 regions ----
        if (lane == 0) {
            const float4 b0 = *reinterpret_cast<const float4*>(&bmbuf[wib][0]);
            const float4 b1 = *reinterpret_cast<const float4*>(&bmbuf[wib][4]);
            const float4 b2 = *reinterpret_cast<const float4*>(&bmbuf[wib][8]);
            float full = fmaxf(fmaxf(fmaxf(b0.x, b0.y), fmaxf(b0.z, b0.w)),
                               fmaxf(fmaxf(b1.x, b1.y), fmaxf(b1.z, b1.w)));
            full = fmaxf(full, fmaxf(fmaxf(b2.x, b2.y), fmaxf(b2.z, b2.w)));

            const float4 q0 = *reinterpret_cast<const float4*>(&rsum[wib][0]);
            const float4 q1 = *reinterpret_cast<const float4*>(&rsum[wib][4]);
            const float4 q2 = *reinterpret_cast<const float4*>(&rsum[wib][8]);
            const float4 q3 = *reinterpret_cast<const float4*>(&rsum[wib][12]);
            const float4 q4 = *reinterpret_cast<const float4*>(&rsum[wib][16]);
            float acc = ((q0.x + q0.y) + (q0.z + q0.w))
                      + ((q1.x + q1.y) + (q1.z + q1.w))
                      + ((q2.x + q2.y) + (q2.z + q2.w))
                      + ((q3.x + q3.y) + (q3.z + q3.w))
                      + ((q4.x + q4.y) + (q4.z + q4.w))
                      + full;
            out[tbase + it] = acc;
        }
        __syncwarp();
    }
}

extern "C" void kernel_launch(void* const* d_in, const int* in_sizes, int n_in,
                              void* d_out, int out_size) {
    const float* x = (const float*)d_in[0];
    float* out = (float*)d_out;
    (void)in_sizes; (void)n_in; (void)out_size;
    // Opt-in dynamic smem above 48KB (idempotent host call; no allocation).
    cudaFuncSetAttribute(rmac_kernel,
                         cudaFuncAttributeMaxDynamicSharedMemorySize, DYN_SMEM);
    rmac_kernel<<<NTILES / (WPB * TPW), 32 * WPB, DYN_SMEM>>>(x, out);
}

// round 13
// speedup vs baseline: 1.5762x; 1.1405x over previous
#include <cuda_runtime.h>
#include <cstdint>

// R-MAC over x[32, 2048, 32, 32] -> out[32, 2048].
// 19 static regions (H=W=32): 1x full (32x32), 6x 21x21 (rows {0,5,11} x cols
// {0,11}), 12x 16x16 (rows {0,5,10,16} x cols {0,8,16}).
// Column segments: s1=[0,21) s2=[11,32) s3=[0,16) s4=[8,24) s5=[16,32).
// Row-block decomposition:
//   segs 1,2 (fam B): blocks [0,5)[5,11)[11,16)[16,21)[21,26)[26,32)
//   segs 3,4,5 (fam C): blocks [0,5)[5,10)[10,16)[16,21)[21,26)[26,32)
// Full image = max over bmbuf of segs 1,2 (cols [0,21)u[11,32)=[0,32), all rows).
//
// R13 design: pure-burst (no refills) but with maximum phase diversity:
// TPW=DEPTH=2, WPB=4 -> 32 KB ring/block -> 6 independent blocks/SM
// (24 warps/SM), grid 8192 (~9 waves). Blocks de-phase, so some block on
// each SM is always in its load-burst phase; the memory queues never drain.

#define WPB   4
#define DEPTH 2
#define TPW   2
#define NTILES (32 * 2048)
#define DYN_SMEM (WPB * DEPTH * 4096)

__constant__ int c_start[2][6] = {{0, 5, 11, 16, 21, 26}, {0, 5, 10, 16, 21, 26}};
__constant__ int c_sz6[2][6]   = {{0, 1, 0, 0, 0, 1},     {0, 0, 1, 0, 0, 1}};
__constant__ int c_rbase[19] = {0, 0, 6, 1, 7, 2, 8,
                                12, 18, 24, 13, 19, 25, 14, 20, 26, 15, 21, 27};
__constant__ int c_rcnt4[19] = {0, 1, 1, 1, 1, 1, 1, 0, 0, 0, 0, 0, 0, 0, 0, 0, 0, 0, 0};

__device__ __forceinline__ void cpa16(uint32_t dst_smem, const void* src) {
    asm volatile("cp.async.cg.shared.global [%0], [%1], 16;"
                 :: "r"(dst_smem), "l"(src) : "memory");
}
__device__ __forceinline__ void cpa_commit() {
    asm volatile("cp.async.commit_group;" ::: "memory");
}
template <int N>
__device__ __forceinline__ void cpa_wait() {
    asm volatile("cp.async.wait_group %0;" :: "n"(N) : "memory");
}
// All TPW groups are committed up front; before consuming tile #it we need
// <= TPW-1-it groups still pending. Constant-folds under full unroll.
__device__ __forceinline__ void cpa_wait_iter(int it) {
    switch (TPW - 1 - it) {
        case 0: cpa_wait<0>(); break;
        case 1: cpa_wait<1>(); break;
        case 2: cpa_wait<2>(); break;
        case 3: cpa_wait<3>(); break;
        default: cpa_wait<0>(); break;
    }
}

__global__ __launch_bounds__(32 * WPB)
void rmac_kernel(const float* __restrict__ x, float* __restrict__ out) {
    extern __shared__ float4 ring[];      // [WPB][DEPTH][256] float4 = 32 KB
    __shared__ float segm[WPB][32 * 7];   // per-row segment maxes, stride 7
    __shared__ float bmbuf[WPB][32];      // 30 (seg,block) maxes
    __shared__ float rsum[WPB][20];       // region maxes for the final sum

    const int wib  = threadIdx.x >> 5;
    const int lane = threadIdx.x & 31;
    const int wg   = blockIdx.x * WPB + wib;
    const size_t tbase = (size_t)wg * TPW;

    const float4* __restrict__ x4 = reinterpret_cast<const float4*>(x);
    const uint32_t ring0 =
        (uint32_t)__cvta_generic_to_shared(ring) + (uint32_t)(wib * DEPTH * 4096);

    // Write mapping: lane l, op k holds tile quad (k*32+l) = row 4k+(l>>3),
    // 16B-group c=l&7. Store XOR-swizzled: group slot c ^ (row&7).
    const int wrow_a = lane >> 3;
    const int wc     = lane & 7;

    // ---- Prologue burst: issue ALL TPW tiles (one commit group each) ----
#pragma unroll
    for (int d = 0; d < TPW; d++) {
        const float4* src = x4 + (tbase + d) * 256;
        const uint32_t sb = ring0 + (uint32_t)d * 4096;
#pragma unroll
        for (int k = 0; k < 8; k++) {
            const int row = 4 * k + wrow_a;
            const uint32_t dst = sb + (uint32_t)((row * 8 + (wc ^ (row & 7))) * 16);
            cpa16(dst, src + k * 32 + lane);
        }
        cpa_commit();
    }

    const int r  = lane;                  // this lane reduces row r
    const int rx = r & 7;

#pragma unroll
    for (int it = 0; it < TPW; it++) {
        cpa_wait_iter(it);                // tile #it complete (slot == it)
        __syncwarp();                     // publish all lanes' copies

        // ---- Row reduce straight from swizzled smem (lane = row) ----
        const float4* B = ring + (size_t)(wib * DEPTH + it) * 256 + r * 8;
        float4 q[8];
#pragma unroll
        for (int g = 0; g < 8; g++) q[g] = B[g ^ rx];   // conflict-free LDS.128
        float m[8];
#pragma unroll
        for (int g = 0; g < 8; g++)
            m[g] = fmaxf(fmaxf(q[g].x, q[g].y), fmaxf(q[g].z, q[g].w));
        const float r11 = q[2].w;         // col 11
        const float r20 = q[5].x;         // col 20

        const float s3 = fmaxf(fmaxf(m[0], m[1]), fmaxf(m[2], m[3]));  // [0,16)
        const float s4 = fmaxf(fmaxf(m[2], m[3]), fmaxf(m[4], m[5]));  // [8,24)
        const float s5 = fmaxf(fmaxf(m[4], m[5]), fmaxf(m[6], m[7]));  // [16,32)
        const float s1 = fmaxf(s3, fmaxf(m[4], r20));                  // [0,21)
        const float s2 = fmaxf(r11, fmaxf(m[3], s5));                  // [11,32)

        float* sd = segm[wib] + r * 7;    // stride 7: conflict-free
        sd[1] = s1; sd[2] = s2; sd[3] = s3; sd[4] = s4; sd[5] = s5;
        __syncwarp();

        // ---- 30 (segment, row-block) maxes ----
        if (lane < 30) {
            const int s   = 1 + lane / 6;
            const int blk = lane % 6;
            const int fam = (s >= 3);
            const int st  = c_start[fam][blk];
            const float* sp = segm[wib] + s;
            float bm = sp[st * 7];
#pragma unroll
            for (int qq = 1; qq < 5; qq++) bm = fmaxf(bm, sp[(st + qq) * 7]);
            if (c_sz6[fam][blk]) bm = fmaxf(bm, sp[(st + 5) * 7]);
            bmbuf[wib][lane] = bm;
        }
        __syncwarp();

        // ---- Region maxes into rsum (lanes 0/19 zero-pad) ----
        if (lane >= 1 && lane < 19) {
            const float* bp = bmbuf[wib];
            const int base = c_rbase[lane];
            float mm = fmaxf(fmaxf(bp[base], bp[base + 1]), bp[base + 2]);
            if (c_rcnt4[lane]) mm = fmaxf(mm, bp[base + 3]);
            rsum[wib][lane] = mm;
        } else if (lane == 19) {
            rsum[wib][19] = 0.0f;
        } else if (lane == 0) {
            rsum[wib][0] = 0.0f;
        }
        __syncwarp();

        // ---- Lane 0: full-image max + sum of 19 regions ----
        if (lane == 0) {
            const float4 b0 = *reinterpret_cast<const float4*>(&bmbuf[wib][0]);
            const float4 b1 = *reinterpret_cast<const float4*>(&bmbuf[wib][4]);
            const float4 b2 = *reinterpret_cast<const float4*>(&bmbuf[wib][8]);
            float full = fmaxf(fmaxf(fmaxf(b0.x, b0.y), fmaxf(b0.z, b0.w)),
                               fmaxf(fmaxf(b1.x, b1.y), fmaxf(b1.z, b1.w)));
            full = fmaxf(full, fmaxf(fmaxf(b2.x, b2.y), fmaxf(b2.z, b2.w)));

            const float4 q0 = *reinterpret_cast<const float4*>(&rsum[wib][0]);
            const float4 q1 = *reinterpret_cast<const float4*>(&rsum[wib][4]);
            const float4 q2 = *reinterpret_cast<const float4*>(&rsum[wib][8]);
            const float4 q3 = *reinterpret_cast<const float4*>(&rsum[wib][12]);
            const float4 q4 = *reinterpret_cast<const float4*>(&rsum[wib][16]);
            float acc = ((q0.x + q0.y) + (q0.z + q0.w))
                      + ((q1.x + q1.y) + (q1.z + q1.w))
                      + ((q2.x + q2.y) + (q2.z + q2.w))
                      + ((q3.x + q3.y) + (q3.z + q3.w))
                      + ((q4.x + q4.y) + (q4.z + q4.w))
                      + full;
            out[tbase + it] = acc;
        }
        __syncwarp();
    }
}

extern "C" void kernel_launch(void* const* d_in, const int* in_sizes, int n_in,
                              void* d_out, int out_size) {
    const float* x = (const float*)d_in[0];
    float* out = (float*)d_out;
    (void)in_sizes; (void)n_in; (void)out_size;
    // Opt-in dynamic smem above 48KB not needed here (32 KB), but harmless
    // to keep the attribute in case static smem pushes past defaults.
    cudaFuncSetAttribute(rmac_kernel,
                         cudaFuncAttributeMaxDynamicSharedMemorySize, DYN_SMEM);
    rmac_kernel<<<NTILES / (WPB * TPW), 32 * WPB, DYN_SMEM>>>(x, out);
}